// round 7
// baseline (speedup 1.0000x reference)
#include <cuda_runtime.h>
#include <cuda_fp16.h>
#include <stdint.h>

#define N_NODES 1000000
#define F 16
#define MAX_E 4000000
#define SCAN_B 1024

// Scratch (allocation-free rule: __device__ globals)
__device__ __half g_hs[(size_t)N_NODES * F];  // h*dinv[src], fp16 (32MB)
__device__ float  g_dinv[N_NODES];            // rsqrt(deg+1)
__device__ int    g_cnt[N_NODES];             // histogram, then scatter cursors
__device__ int2   g_seg[N_NODES];             // (begin, end) of dst segment
__device__ int    g_total;                    // running base for block offsets
__device__ int    g_src[MAX_E];               // src ids grouped by dst

// ---------------------------------------------------------------------------
// K0: zero histogram (+ global base counter)
// ---------------------------------------------------------------------------
__global__ void k_zero(int n4) {
    int i = blockIdx.x * blockDim.x + threadIdx.x;
    if (i < n4) reinterpret_cast<int4*>(g_cnt)[i] = make_int4(0, 0, 0, 0);
    if (i == 0) g_total = 0;
}

// ---------------------------------------------------------------------------
// K1: histogram of dst (= degree without self loop)
// ---------------------------------------------------------------------------
__global__ void k_hist(const int* __restrict__ col, int E, int n) {
    int e = blockIdx.x * blockDim.x + threadIdx.x;
    if (e < E) {
        int c = col[e];
        if ((unsigned)c < (unsigned)n) atomicAdd(&g_cnt[c], 1);
    }
}

// ---------------------------------------------------------------------------
// K2: single-kernel exclusive scan. Warp-shuffle block scan; block base via
// atomicAdd on g_total (segments permuted across blocks -> harmless, the
// final per-node sum is order-free). Also writes dinv.
// ---------------------------------------------------------------------------
__global__ void __launch_bounds__(SCAN_B)
k_scan(int n) {
    __shared__ int wsum[32];
    __shared__ int sbase;

    int i    = blockIdx.x * SCAN_B + threadIdx.x;
    int lane = threadIdx.x & 31;
    int wid  = threadIdx.x >> 5;

    int v = (i < n) ? g_cnt[i] : 0;

    // inclusive warp scan
    int x = v;
#pragma unroll
    for (int d = 1; d < 32; d <<= 1) {
        int t = __shfl_up_sync(0xffffffffu, x, d);
        if (lane >= d) x += t;
    }
    if (lane == 31) wsum[wid] = x;
    __syncthreads();

    if (wid == 0) {
        int w = wsum[lane];
#pragma unroll
        for (int d = 1; d < 32; d <<= 1) {
            int t = __shfl_up_sync(0xffffffffu, w, d);
            if (lane >= d) w += t;
        }
        wsum[lane] = w;                       // inclusive warp-sum scan
        if (lane == 31) sbase = atomicAdd(&g_total, w);  // block base
    }
    __syncthreads();

    if (i < n) {
        int excl = x - v + (wid ? wsum[wid - 1] : 0) + sbase;
        g_seg[i]  = make_int2(excl, excl + v);
        g_dinv[i] = rsqrtf((float)v + 1.0f);
    }
}

// ---------------------------------------------------------------------------
// K3 (fused): blocks [0, gh) compute h_scaled = (x@W)*dinv -> fp16;
//             blocks [gh, ...) scatter src ids into dst segments.
// The two halves are independent and overlap on the chip.
// ---------------------------------------------------------------------------
__global__ void __launch_bounds__(256)
k_mid(const float4* __restrict__ x4, const float* __restrict__ W,
      const int* __restrict__ ei, int E, int n, int gh) {
    if ((int)blockIdx.x < gh) {
        __shared__ float sW[F * F];
        sW[threadIdx.x] = W[threadIdx.x];     // blockDim == 256 == F*F
        __syncthreads();

        int i = blockIdx.x * 256 + threadIdx.x;
        if (i >= n) return;

        float4 xv0 = x4[(size_t)i * 4 + 0];
        float4 xv1 = x4[(size_t)i * 4 + 1];
        float4 xv2 = x4[(size_t)i * 4 + 2];
        float4 xv3 = x4[(size_t)i * 4 + 3];
        float xr[F] = {xv0.x, xv0.y, xv0.z, xv0.w,
                       xv1.x, xv1.y, xv1.z, xv1.w,
                       xv2.x, xv2.y, xv2.z, xv2.w,
                       xv3.x, xv3.y, xv3.z, xv3.w};

        float acc[F];
#pragma unroll
        for (int j = 0; j < F; j++) acc[j] = 0.0f;
#pragma unroll
        for (int k = 0; k < F; k++) {
            float xk = xr[k];
#pragma unroll
            for (int j = 0; j < F; j++) acc[j] = fmaf(xk, sW[k * F + j], acc[j]);
        }

        float di = g_dinv[i];                 // coalesced

        uint4 hpk[2];
        __half2* hh = reinterpret_cast<__half2*>(&hpk[0]);
#pragma unroll
        for (int q = 0; q < 8; q++)
            hh[q] = __floats2half2_rn(acc[2 * q] * di, acc[2 * q + 1] * di);
        uint4* hp = reinterpret_cast<uint4*>(g_hs + (size_t)i * F);
        hp[0] = hpk[0];
        hp[1] = hpk[1];
    } else {
        int e = ((int)blockIdx.x - gh) * 256 + threadIdx.x;
        if (e >= E) return;
        int r = ei[e];
        int c = ei[(size_t)E + e];
        if ((unsigned)r >= (unsigned)n || (unsigned)c >= (unsigned)n) return;
        int k = atomicSub(&g_cnt[c], 1) - 1;  // unique slot 0..deg-1
        g_src[__ldg(&g_seg[c].x) + k] = r;
    }
}

// ---------------------------------------------------------------------------
// K4: per-dst gather, 4 threads per node (feature split, 8B quarters).
// out = di * (sum_{s in seg} h_scaled[s] + h_scaled[i]) + b.  No per-edge
// dinv gather (folded into h_scaled).
// ---------------------------------------------------------------------------
__global__ void __launch_bounds__(256)
k_out(const float* __restrict__ b, float4* __restrict__ out4, int n) {
    int tid  = threadIdx.x;
    int lane = tid & 3;
    int i    = blockIdx.x * 64 + (tid >> 2);
    if (i >= n) return;

    float4 bq = reinterpret_cast<const float4*>(b)[lane];

    int2 seg = __ldg(&g_seg[i]);
    float di = g_dinv[i];

    float4 acc = make_float4(0.f, 0.f, 0.f, 0.f);

    int j = seg.x;
    for (; j + 2 <= seg.y; j += 2) {
        int sA = __ldg(&g_src[j]);
        int sB = __ldg(&g_src[j + 1]);
        uint2 pA = __ldg(&reinterpret_cast<const uint2*>(g_hs + (size_t)sA * F)[lane]);
        uint2 pB = __ldg(&reinterpret_cast<const uint2*>(g_hs + (size_t)sB * F)[lane]);
        float2 a0 = __half22float2(*reinterpret_cast<const __half2*>(&pA.x));
        float2 a1 = __half22float2(*reinterpret_cast<const __half2*>(&pA.y));
        float2 b0 = __half22float2(*reinterpret_cast<const __half2*>(&pB.x));
        float2 b1 = __half22float2(*reinterpret_cast<const __half2*>(&pB.y));
        acc.x += a0.x + b0.x;
        acc.y += a0.y + b0.y;
        acc.z += a1.x + b1.x;
        acc.w += a1.y + b1.y;
    }
    if (j < seg.y) {
        int s = __ldg(&g_src[j]);
        uint2 p = __ldg(&reinterpret_cast<const uint2*>(g_hs + (size_t)s * F)[lane]);
        float2 f0 = __half22float2(*reinterpret_cast<const __half2*>(&p.x));
        float2 f1 = __half22float2(*reinterpret_cast<const __half2*>(&p.y));
        acc.x += f0.x;
        acc.y += f0.y;
        acc.z += f1.x;
        acc.w += f1.y;
    }

    // self-loop: h_scaled[i] added, then everything * di
    uint2 pi = reinterpret_cast<const uint2*>(g_hs + (size_t)i * F)[lane];
    float2 v0 = __half22float2(*reinterpret_cast<const __half2*>(&pi.x));
    float2 v1 = __half22float2(*reinterpret_cast<const __half2*>(&pi.y));
    acc.x += v0.x;
    acc.y += v0.y;
    acc.z += v1.x;
    acc.w += v1.y;

    out4[(size_t)i * 4 + lane] = make_float4(
        fmaf(acc.x, di, bq.x),
        fmaf(acc.y, di, bq.y),
        fmaf(acc.z, di, bq.z),
        fmaf(acc.w, di, bq.w));
}

// ---------------------------------------------------------------------------
// launch
// ---------------------------------------------------------------------------
extern "C" void kernel_launch(void* const* d_in, const int* in_sizes, int n_in,
                              void* d_out, int out_size) {
    const float* x   = (const float*)d_in[0];
    const int*   ei  = (const int*)d_in[1];  // int32 (JAX x64 disabled)
    const float* W   = (const float*)d_in[2];
    const float* b   = (const float*)d_in[3];
    float*       out = (float*)d_out;

    int n = in_sizes[0] / F;   // 1,000,000
    int E = in_sizes[1] / 2;   // 4,000,000
    if (E > MAX_E) E = MAX_E;

    const int T = 256;
    int n4 = (n + 3) / 4;
    int gh = (n + T - 1) / T;          // h-part blocks
    int gs = (E + T - 1) / T;          // scatter-part blocks

    k_zero<<<(n4 + T - 1) / T, T>>>(n4);
    k_hist<<<(E + T - 1) / T, T>>>(ei + (size_t)E, E, n);
    k_scan<<<(n + SCAN_B - 1) / SCAN_B, SCAN_B>>>(n);
    k_mid<<<gh + gs, T>>>((const float4*)x, W, ei, E, n, gh);
    k_out<<<(n * 4 + T - 1) / T, T>>>(b, (float4*)out, n);
}